// round 9
// baseline (speedup 1.0000x reference)
#include <cuda_runtime.h>
#include <cuda_fp16.h>
#include <cstdint>

#define N_NODES 100000
#define N_EDGES 1600000
#define N_GRAPHS 512
#define DF 128
#define EPS 1e-5f
#define SCAN_BLK 1024
#define SCAN_NBLK ((N_NODES + SCAN_BLK - 1) / SCAN_BLK)   // 98

// GEMM-TC tile config
#define XS_STRIDE 132
#define WS_STRIDE 136
#define SMEM_TC (64 * XS_STRIDE * 4 + 128 * WS_STRIDE * 4)   // 103424 B

// ---------------- scratch (no allocations allowed) ----------------
__device__ __half2 g_h16[N_NODES * (DF / 2)];  // (x @ W) * dinv[row], fp16
__device__ float g_xA [N_NODES * DF];   // ping
__device__ float g_xB [N_NODES * DF];   // pong
__device__ float g_dinv[N_NODES];
__device__ int   g_cnt [N_NODES];
__device__ int   g_off [N_NODES + 1];
__device__ int   g_cur [N_NODES];
__device__ int   g_csr [N_EDGES];       // src ids bucketed by dst
__device__ float g_feat[N_GRAPHS * 2 * DF];
__device__ float g_sc[3][DF];           // BN scale  per layer/col
__device__ float g_tc[3][DF];           // BN offset per layer/col
__device__ int   g_bsum[SCAN_NBLK];
__device__ int   g_bbase[SCAN_NBLK];

__device__ __forceinline__ float* bufsel(int s) {
    return (s == 1) ? g_xA : g_xB;
}

// ---------------- BN constant precompute ----------------
struct BNP {
    const float* g[3]; const float* v[3]; const float* c[3];
    const float* m[3]; const float* b[3];
};

__global__ void k_prep(BNP p) {
    int t = threadIdx.x;          // 0..383
    int l = t >> 7, c = t & 127;
    float sc = p.g[l][c] * rsqrtf(p.v[l][c] + EPS);
    g_sc[l][c] = sc;
    g_tc[l][c] = (p.c[l][c] - p.m[l][c]) * sc + p.b[l][c];
}

// ---------------- CSR build ----------------
__global__ void k_zero_cnt() {
    int i = blockIdx.x * blockDim.x + threadIdx.x;
    if (i < N_NODES) g_cnt[i] = 0;
}

__global__ void k_count(const int* __restrict__ ei) {
    int e = blockIdx.x * blockDim.x + threadIdx.x;
    if (e < N_EDGES) atomicAdd(&g_cnt[ei[N_EDGES + e]], 1);
}

// hierarchical scan stage A
__global__ void k_scanA() {
    __shared__ int sh[SCAN_BLK];
    int t = threadIdx.x;
    int b = blockIdx.x;
    int i = b * SCAN_BLK + t;
    int c = (i < N_NODES) ? g_cnt[i] : 0;
    sh[t] = c;
    __syncthreads();
#pragma unroll
    for (int d = 1; d < SCAN_BLK; d <<= 1) {
        int add = (t >= d) ? sh[t - d] : 0;
        __syncthreads();
        sh[t] += add;
        __syncthreads();
    }
    if (i < N_NODES) g_off[i] = sh[t] - c;
    if (t == SCAN_BLK - 1) g_bsum[b] = sh[t];
}

__global__ void k_scanB() {
    __shared__ int sh[128];
    int t = threadIdx.x;
    int v = (t < SCAN_NBLK) ? g_bsum[t] : 0;
    sh[t] = v;
    __syncthreads();
#pragma unroll
    for (int d = 1; d < 128; d <<= 1) {
        int add = (t >= d) ? sh[t - d] : 0;
        __syncthreads();
        sh[t] += add;
        __syncthreads();
    }
    if (t < SCAN_NBLK) g_bbase[t] = sh[t] - v;
    if (t == 127) g_off[N_NODES] = sh[127];
}

__global__ void k_scanC() {
    int t = threadIdx.x;
    int b = blockIdx.x;
    int i = b * SCAN_BLK + t;
    if (i < N_NODES) {
        int off = g_off[i] + g_bbase[b];
        g_off[i] = off;
        g_cur[i] = off;
        g_dinv[i] = rsqrtf((float)g_cnt[i] + 1.0f);
    }
}

__global__ void k_fill(const int* __restrict__ ei) {
    int e = blockIdx.x * blockDim.x + threadIdx.x;
    if (e < N_EDGES) {
        int src = ei[e];
        int dst = ei[N_EDGES + e];
        int pos = atomicAdd(&g_cur[dst], 1);
        g_csr[pos] = src;
    }
}

// ------- GEMM via mma.sync m16n8k8 tf32: g_h16 = fp16((x@W)*dinv) ---------
// block 128 thr (4 warps), each warp a 16x128 tile; block covers 64 rows.
__device__ __forceinline__ unsigned f2tf32(float f) {
    unsigned u;
    asm("cvt.rna.tf32.f32 %0, %1;" : "=r"(u) : "f"(f));
    return u;
}

__global__ void __launch_bounds__(128) k_gemm_tc(const float* __restrict__ xext,
                                                 const float* __restrict__ W,
                                                 int in_sel) {
    const float* __restrict__ x = (in_sel == 0) ? xext : bufsel(in_sel);
    extern __shared__ float smem[];
    float* xs = smem;                                    // [64][XS_STRIDE]
    unsigned* ws = (unsigned*)(smem + 64 * XS_STRIDE);   // [128][WS_STRIDE] tf32

    int tid = threadIdx.x;
    int wy = tid >> 5;
    int lane = tid & 31;
    int g = lane >> 2;      // 0..7
    int t4 = lane & 3;      // 0..3
    int row0 = blockIdx.x * 64;

    // load W -> tf32 shared (coalesced)
    for (int i = tid; i < DF * DF; i += 128) {
        int k = i >> 7, n = i & 127;
        ws[k * WS_STRIDE + n] = f2tf32(W[i]);
    }
    // load x tile (64 rows), zero-pad past N
    for (int i = tid; i < 64 * 32; i += 128) {
        int r = i >> 5;
        int c4 = (i & 31) * 4;
        float4 v = make_float4(0.f, 0.f, 0.f, 0.f);
        if (row0 + r < N_NODES)
            v = __ldcs((const float4*)(x + (size_t)(row0 + r) * DF + c4));
        float* dst = xs + r * XS_STRIDE + c4;
        dst[0] = v.x; dst[1] = v.y; dst[2] = v.z; dst[3] = v.w;
    }
    __syncthreads();

    float c[16][4];
#pragma unroll
    for (int nt = 0; nt < 16; nt++) {
        c[nt][0] = 0.f; c[nt][1] = 0.f; c[nt][2] = 0.f; c[nt][3] = 0.f;
    }

    const float* xw = xs + (wy * 16) * XS_STRIDE;
#pragma unroll
    for (int ks = 0; ks < 16; ks++) {
        int kc = ks * 8 + t4;
        unsigned a0 = f2tf32(xw[g * XS_STRIDE + kc]);
        unsigned a1 = f2tf32(xw[(g + 8) * XS_STRIDE + kc]);
        unsigned a2 = f2tf32(xw[g * XS_STRIDE + kc + 4]);
        unsigned a3 = f2tf32(xw[(g + 8) * XS_STRIDE + kc + 4]);
        const unsigned* wk = ws + (size_t)kc * WS_STRIDE;
#pragma unroll
        for (int nt = 0; nt < 16; nt++) {
            unsigned b0 = wk[nt * 8 + g];
            unsigned b1 = wk[4 * WS_STRIDE + nt * 8 + g];
            asm volatile(
                "mma.sync.aligned.m16n8k8.row.col.f32.tf32.tf32.f32 "
                "{%0,%1,%2,%3}, {%4,%5,%6,%7}, {%8,%9}, {%0,%1,%2,%3};"
                : "+f"(c[nt][0]), "+f"(c[nt][1]), "+f"(c[nt][2]), "+f"(c[nt][3])
                : "r"(a0), "r"(a1), "r"(a2), "r"(a3), "r"(b0), "r"(b1));
        }
    }

    // epilogue: scale by dinv, pack half2, store
    int row_a = row0 + wy * 16 + g;
    int row_b = row_a + 8;
    float dva = (row_a < N_NODES) ? g_dinv[row_a] : 0.f;
    float dvb = (row_b < N_NODES) ? g_dinv[row_b] : 0.f;
#pragma unroll
    for (int nt = 0; nt < 16; nt++) {
        int cidx = nt * 4 + t4;   // half2 column index (cols 2c, 2c+1)
        if (row_a < N_NODES)
            g_h16[(size_t)row_a * 64 + cidx] =
                __floats2half2_rn(c[nt][0] * dva, c[nt][1] * dva);
        if (row_b < N_NODES)
            g_h16[(size_t)row_b * 64 + cidx] =
                __floats2half2_rn(c[nt][2] * dvb, c[nt][3] * dvb);
    }
}

// ------- gather + BN + ReLU + residual: ONE warp per node, pair scheme -----
__global__ void k_gather(int layer, int prev_sel, int out_sel) {
    int node = (blockIdx.x * blockDim.x + threadIdx.x) >> 5;
    int lane = threadIdx.x & 31;
    if (node >= N_NODES) return;
    int hl = lane >> 4;
    int lh = lane & 15;

    int beg = g_off[node];
    int end = g_off[node + 1];

    const uint4* __restrict__ H = (const uint4*)g_h16;

    float acc[8];
#pragma unroll
    for (int j = 0; j < 8; j++) acc[j] = 0.0f;

    if (hl == 0) {
        uint4 q = H[(size_t)node * 16 + lh];
        float2 u0 = __half22float2(*(__half2*)&q.x);
        float2 u1 = __half22float2(*(__half2*)&q.y);
        float2 u2 = __half22float2(*(__half2*)&q.z);
        float2 u3 = __half22float2(*(__half2*)&q.w);
        acc[0] = u0.x; acc[1] = u0.y; acc[2] = u1.x; acc[3] = u1.y;
        acc[4] = u2.x; acc[5] = u2.y; acc[6] = u3.x; acc[7] = u3.y;
    }

    for (int j0 = beg; j0 < end; j0 += 32) {
        int cntc = min(end - j0, 32);
        int idx = (lane < cntc) ? g_csr[j0 + lane] : 0;
        int steps = (cntc + 1) >> 1;
        for (int k = 0; k < steps; k++) {
            int e = 2 * k + hl;
            int srcl = (e < cntc) ? e : 0;
            int s = __shfl_sync(0xffffffffu, idx, srcl);
            if (e < cntc) {
                uint4 q = H[(size_t)s * 16 + lh];
                float2 u0 = __half22float2(*(__half2*)&q.x);
                float2 u1 = __half22float2(*(__half2*)&q.y);
                float2 u2 = __half22float2(*(__half2*)&q.z);
                float2 u3 = __half22float2(*(__half2*)&q.w);
                acc[0] += u0.x; acc[1] += u0.y; acc[2] += u1.x; acc[3] += u1.y;
                acc[4] += u2.x; acc[5] += u2.y; acc[6] += u3.x; acc[7] += u3.y;
            }
        }
    }

#pragma unroll
    for (int j = 0; j < 8; j++)
        acc[j] += __shfl_xor_sync(0xffffffffu, acc[j], 16);

    float di = g_dinv[node];
    int cb4 = 8 * lh + 4 * hl;
    int o = 4 * hl;

    float4 SC = *(const float4*)&g_sc[layer][cb4];
    float4 TC = *(const float4*)&g_tc[layer][cb4];

    float4 r;
    r.x = fmaxf(fmaf(acc[o + 0] * di, SC.x, TC.x), 0.0f);
    r.y = fmaxf(fmaf(acc[o + 1] * di, SC.y, TC.y), 0.0f);
    r.z = fmaxf(fmaf(acc[o + 2] * di, SC.z, TC.z), 0.0f);
    r.w = fmaxf(fmaf(acc[o + 3] * di, SC.w, TC.w), 0.0f);

    if (prev_sel != 0) {
        float4 p = __ldcs((const float4*)(bufsel(prev_sel) + (size_t)node * DF + cb4));
        r.x += p.x; r.y += p.y; r.z += p.z; r.w += p.w;
    }
    __stcs((float4*)(bufsel(out_sel) + (size_t)node * DF + cb4), r);
}

// ---------------- pooling ----------------
__global__ void k_pool(int x_sel) {
    const float* __restrict__ x = bufsel(x_sel);
    int g = blockIdx.x;
    int t = threadIdx.x;
    int start = (int)(((long long)g * N_NODES + N_GRAPHS - 1) / N_GRAPHS);
    int end   = (int)(((long long)(g + 1) * N_NODES + N_GRAPHS - 1) / N_GRAPHS);
    float sum = 0.0f, mx = -3.4e38f;
    for (int n = start; n < end; n++) {
        float val = __ldcs(&x[(size_t)n * DF + t]);
        sum += val;
        mx = fmaxf(mx, val);
    }
    g_feat[g * 2 * DF + t]      = sum / (float)(end - start);
    g_feat[g * 2 * DF + DF + t] = mx;
}

// ---------------- MLP head ----------------
__global__ void k_mlp(const float* __restrict__ L1w, const float* __restrict__ L1b,
                      const float* __restrict__ L2w, const float* __restrict__ L2b,
                      const float* __restrict__ L3w, const float* __restrict__ L3b,
                      float* __restrict__ out) {
    int g = blockIdx.x;
    int t = threadIdx.x;
    __shared__ float feat[2 * DF];
    __shared__ float h1[DF];
    __shared__ float h2[DF / 2];

    feat[t]      = g_feat[g * 2 * DF + t];
    feat[t + DF] = g_feat[g * 2 * DF + DF + t];
    __syncthreads();

    float a = L1b[t];
#pragma unroll 8
    for (int k = 0; k < 2 * DF; k++)
        a = fmaf(feat[k], L1w[k * DF + t], a);
    h1[t] = fmaxf(a, 0.0f);
    __syncthreads();

    if (t < DF / 2) {
        float a2 = L2b[t];
#pragma unroll 8
        for (int k = 0; k < DF; k++)
            a2 = fmaf(h1[k], L2w[k * (DF / 2) + t], a2);
        h2[t] = fmaxf(a2, 0.0f);
    }
    __syncthreads();

    if (t == 0) {
        float o = L3b[0];
#pragma unroll
        for (int k = 0; k < DF / 2; k++)
            o = fmaf(h2[k], L3w[k], o);
        out[g] = o;
    }
}

// ---------------- launch ----------------
extern "C" void kernel_launch(void* const* d_in, const int* in_sizes, int n_in,
                              void* d_out, int out_size) {
    const float* x  = (const float*)d_in[0];
    const int*   ei = (const int*)d_in[1];   // int32 (JAX x64 disabled)
    const float* W[3]  = {(const float*)d_in[3],  (const float*)d_in[9],  (const float*)d_in[15]};
    const float* cb[3] = {(const float*)d_in[4],  (const float*)d_in[10], (const float*)d_in[16]};
    const float* gg[3] = {(const float*)d_in[5],  (const float*)d_in[11], (const float*)d_in[17]};
    const float* bt[3] = {(const float*)d_in[6],  (const float*)d_in[12], (const float*)d_in[18]};
    const float* m[3]  = {(const float*)d_in[7],  (const float*)d_in[13], (const float*)d_in[19]};
    const float* v[3]  = {(const float*)d_in[8],  (const float*)d_in[14], (const float*)d_in[20]};
    const float* L1w = (const float*)d_in[21];
    const float* L1b = (const float*)d_in[22];
    const float* L2w = (const float*)d_in[23];
    const float* L2b = (const float*)d_in[24];
    const float* L3w = (const float*)d_in[25];
    const float* L3b = (const float*)d_in[26];
    float* out = (float*)d_out;

    cudaFuncSetAttribute(k_gemm_tc, cudaFuncAttributeMaxDynamicSharedMemorySize,
                         SMEM_TC);

    // BN constants
    BNP bnp;
    for (int i = 0; i < 3; i++) {
        bnp.g[i] = gg[i]; bnp.v[i] = v[i]; bnp.c[i] = cb[i];
        bnp.m[i] = m[i];  bnp.b[i] = bt[i];
    }
    k_prep<<<1, 384>>>(bnp);

    // CSR build + dinv
    k_zero_cnt<<<(N_NODES + 255) / 256, 256>>>();
    k_count<<<(N_EDGES + 255) / 256, 256>>>(ei);
    k_scanA<<<SCAN_NBLK, SCAN_BLK>>>();
    k_scanB<<<1, 128>>>();
    k_scanC<<<SCAN_NBLK, SCAN_BLK>>>();
    k_fill<<<(N_EDGES + 255) / 256, 256>>>(ei);

    const int gemm_grid   = (N_NODES + 63) / 64;             // 1563
    const int gather_grid = (N_NODES * 32 + 255) / 256;      // 12500

    // layer 0
    k_gemm_tc<<<gemm_grid, 128, SMEM_TC>>>(x, W[0], 0);
    k_gather<<<gather_grid, 256>>>(0, 0, 1);

    // layer 1
    k_gemm_tc<<<gemm_grid, 128, SMEM_TC>>>(nullptr, W[1], 1);
    k_gather<<<gather_grid, 256>>>(1, 1, 2);

    // layer 2
    k_gemm_tc<<<gemm_grid, 128, SMEM_TC>>>(nullptr, W[2], 2);
    k_gather<<<gather_grid, 256>>>(2, 2, 1);

    // pooling + MLP head
    k_pool<<<N_GRAPHS, DF>>>(1);
    k_mlp<<<N_GRAPHS, DF>>>(L1w, L1b, L2w, L2b, L3w, L3b, out);
}

// round 10
// speedup vs baseline: 1.7151x; 1.7151x over previous
#include <cuda_runtime.h>
#include <cuda_fp16.h>
#include <cstdint>

#define N_NODES 100000
#define N_EDGES 1600000
#define N_GRAPHS 512
#define DF 128
#define EPS 1e-5f
#define SCAN_BLK 1024
#define SCAN_NBLK ((N_NODES + SCAN_BLK - 1) / SCAN_BLK)   // 98
#define XS_STRIDE 132
#define N_TILES (N_NODES / 32)          // 3125 exact
#define GEMM_BLOCKS 296

// ---------------- scratch (no allocations allowed) ----------------
__device__ __half2 g_h16[N_NODES * (DF / 2)];  // (x @ W) * dinv[row], fp16
__device__ float g_xA [N_NODES * DF];   // ping
__device__ float g_xB [N_NODES * DF];   // pong
__device__ float g_dinv[N_NODES];
__device__ int   g_cnt [N_NODES];
__device__ int   g_off [N_NODES + 1];
__device__ int   g_cur [N_NODES];
__device__ int   g_csr [N_EDGES];       // src ids bucketed by dst
__device__ float g_feat[N_GRAPHS * 2 * DF];
__device__ float g_sc[3][DF];           // BN scale  per layer/col
__device__ float g_tc[3][DF];           // BN offset per layer/col
__device__ int   g_bsum[SCAN_NBLK];
__device__ int   g_bbase[SCAN_NBLK];

__device__ __forceinline__ float* bufsel(int s) {
    return (s == 1) ? g_xA : g_xB;
}

// ---------------- BN constant precompute ----------------
struct BNP {
    const float* g[3]; const float* v[3]; const float* c[3];
    const float* m[3]; const float* b[3];
};

__global__ void k_prep(BNP p) {
    int t = threadIdx.x;          // 0..383
    int l = t >> 7, c = t & 127;
    float sc = p.g[l][c] * rsqrtf(p.v[l][c] + EPS);
    g_sc[l][c] = sc;
    g_tc[l][c] = (p.c[l][c] - p.m[l][c]) * sc + p.b[l][c];
}

// ---------------- CSR build ----------------
__global__ void k_zero_cnt() {
    int i = blockIdx.x * blockDim.x + threadIdx.x;
    if (i < N_NODES) g_cnt[i] = 0;
}

__global__ void k_count(const int* __restrict__ ei) {
    int e = blockIdx.x * blockDim.x + threadIdx.x;
    if (e < N_EDGES) atomicAdd(&g_cnt[ei[N_EDGES + e]], 1);
}

__global__ void k_scanA() {
    __shared__ int sh[SCAN_BLK];
    int t = threadIdx.x;
    int b = blockIdx.x;
    int i = b * SCAN_BLK + t;
    int c = (i < N_NODES) ? g_cnt[i] : 0;
    sh[t] = c;
    __syncthreads();
#pragma unroll
    for (int d = 1; d < SCAN_BLK; d <<= 1) {
        int add = (t >= d) ? sh[t - d] : 0;
        __syncthreads();
        sh[t] += add;
        __syncthreads();
    }
    if (i < N_NODES) g_off[i] = sh[t] - c;
    if (t == SCAN_BLK - 1) g_bsum[b] = sh[t];
}

__global__ void k_scanB() {
    __shared__ int sh[128];
    int t = threadIdx.x;
    int v = (t < SCAN_NBLK) ? g_bsum[t] : 0;
    sh[t] = v;
    __syncthreads();
#pragma unroll
    for (int d = 1; d < 128; d <<= 1) {
        int add = (t >= d) ? sh[t - d] : 0;
        __syncthreads();
        sh[t] += add;
        __syncthreads();
    }
    if (t < SCAN_NBLK) g_bbase[t] = sh[t] - v;
    if (t == 127) g_off[N_NODES] = sh[127];
}

__global__ void k_scanC() {
    int t = threadIdx.x;
    int b = blockIdx.x;
    int i = b * SCAN_BLK + t;
    if (i < N_NODES) {
        int off = g_off[i] + g_bbase[b];
        g_off[i] = off;
        g_cur[i] = off;
        g_dinv[i] = rsqrtf((float)g_cnt[i] + 1.0f);
    }
}

__global__ void k_fill(const int* __restrict__ ei) {
    int e = blockIdx.x * blockDim.x + threadIdx.x;
    if (e < N_EDGES) {
        int src = ei[e];
        int dst = ei[N_EDGES + e];
        int pos = atomicAdd(&g_cur[dst], 1);
        g_csr[pos] = src;
    }
}

// ------- GEMM, tf32 mma.m16n8k8, W-in-registers, grid-stride row tiles ----
__device__ __forceinline__ unsigned f2tf32(float f) {
    unsigned u;
    asm("cvt.rna.tf32.f32 %0, %1;" : "=r"(u) : "f"(f));
    return u;
}

__global__ void __launch_bounds__(128, 2) k_gemm_tc(const float* __restrict__ xext,
                                                    const float* __restrict__ W,
                                                    int in_sel) {
    const float* __restrict__ x = (in_sel == 0) ? xext : bufsel(in_sel);
    __shared__ unsigned xs[32 * XS_STRIDE];   // 16.9 KB, tf32 x tile

    int tid = threadIdx.x;
    int wy = tid >> 5;        // warp owns cols wy*32 .. wy*32+31
    int lane = tid & 31;
    int g = lane >> 2;        // 0..7
    int t4 = lane & 3;        // 0..3

    // ---- load this lane's B fragments ONCE (128 tf32 regs) ----
    unsigned b[16][4][2];
#pragma unroll
    for (int ks = 0; ks < 16; ks++) {
        int k0 = ks * 8 + t4;
#pragma unroll
        for (int nt = 0; nt < 4; nt++) {
            int n = wy * 32 + nt * 8 + g;
            b[ks][nt][0] = f2tf32(W[k0 * DF + n]);
            b[ks][nt][1] = f2tf32(W[(k0 + 4) * DF + n]);
        }
    }

    for (int tile = blockIdx.x; tile < N_TILES; tile += gridDim.x) {
        int row0 = tile * 32;

        // stage x tile -> tf32 smem (conflict-free padded)
#pragma unroll
        for (int i = 0; i < 8; i++) {
            int idx = tid + i * 128;     // 0..1023
            int r = idx >> 5;
            int c4 = (idx & 31) * 4;
            float4 v = __ldcs((const float4*)(x + (size_t)(row0 + r) * DF + c4));
            uint4 tv;
            tv.x = f2tf32(v.x); tv.y = f2tf32(v.y);
            tv.z = f2tf32(v.z); tv.w = f2tf32(v.w);
            *(uint4*)&xs[r * XS_STRIDE + c4] = tv;
        }
        __syncthreads();

        float c[2][4][4];
#pragma unroll
        for (int m = 0; m < 2; m++)
#pragma unroll
            for (int nt = 0; nt < 4; nt++) {
                c[m][nt][0] = 0.f; c[m][nt][1] = 0.f;
                c[m][nt][2] = 0.f; c[m][nt][3] = 0.f;
            }

#pragma unroll
        for (int ks = 0; ks < 16; ks++) {
            int kc = ks * 8 + t4;
#pragma unroll
            for (int m = 0; m < 2; m++) {
                unsigned a0 = xs[(m * 16 + g) * XS_STRIDE + kc];
                unsigned a1 = xs[(m * 16 + g + 8) * XS_STRIDE + kc];
                unsigned a2 = xs[(m * 16 + g) * XS_STRIDE + kc + 4];
                unsigned a3 = xs[(m * 16 + g + 8) * XS_STRIDE + kc + 4];
#pragma unroll
                for (int nt = 0; nt < 4; nt++) {
                    asm volatile(
                        "mma.sync.aligned.m16n8k8.row.col.f32.tf32.tf32.f32 "
                        "{%0,%1,%2,%3}, {%4,%5,%6,%7}, {%8,%9}, {%0,%1,%2,%3};"
                        : "+f"(c[m][nt][0]), "+f"(c[m][nt][1]),
                          "+f"(c[m][nt][2]), "+f"(c[m][nt][3])
                        : "r"(a0), "r"(a1), "r"(a2), "r"(a3),
                          "r"(b[ks][nt][0]), "r"(b[ks][nt][1]));
                }
            }
        }

        // epilogue: scale by dinv, pack half2, store
#pragma unroll
        for (int m = 0; m < 2; m++) {
            int row_a = row0 + m * 16 + g;
            int row_b = row_a + 8;
            float dva = g_dinv[row_a];
            float dvb = g_dinv[row_b];
#pragma unroll
            for (int nt = 0; nt < 4; nt++) {
                int col2 = wy * 16 + nt * 4 + t4;   // half2 unit index
                g_h16[(size_t)row_a * 64 + col2] =
                    __floats2half2_rn(c[m][nt][0] * dva, c[m][nt][1] * dva);
                g_h16[(size_t)row_b * 64 + col2] =
                    __floats2half2_rn(c[m][nt][2] * dvb, c[m][nt][3] * dvb);
            }
        }
        __syncthreads();
    }
}

// ------- gather + BN + ReLU + residual: ONE warp per node, pair scheme -----
__global__ void k_gather(int layer, int prev_sel, int out_sel) {
    int node = (blockIdx.x * blockDim.x + threadIdx.x) >> 5;
    int lane = threadIdx.x & 31;
    if (node >= N_NODES) return;
    int hl = lane >> 4;
    int lh = lane & 15;

    int beg = g_off[node];
    int end = g_off[node + 1];

    const uint4* __restrict__ H = (const uint4*)g_h16;

    float acc[8];
#pragma unroll
    for (int j = 0; j < 8; j++) acc[j] = 0.0f;

    if (hl == 0) {
        uint4 q = H[(size_t)node * 16 + lh];
        float2 u0 = __half22float2(*(__half2*)&q.x);
        float2 u1 = __half22float2(*(__half2*)&q.y);
        float2 u2 = __half22float2(*(__half2*)&q.z);
        float2 u3 = __half22float2(*(__half2*)&q.w);
        acc[0] = u0.x; acc[1] = u0.y; acc[2] = u1.x; acc[3] = u1.y;
        acc[4] = u2.x; acc[5] = u2.y; acc[6] = u3.x; acc[7] = u3.y;
    }

    for (int j0 = beg; j0 < end; j0 += 32) {
        int cntc = min(end - j0, 32);
        int idx = (lane < cntc) ? g_csr[j0 + lane] : 0;
        int steps = (cntc + 1) >> 1;
        for (int k = 0; k < steps; k++) {
            int e = 2 * k + hl;
            int srcl = (e < cntc) ? e : 0;
            int s = __shfl_sync(0xffffffffu, idx, srcl);
            if (e < cntc) {
                uint4 q = H[(size_t)s * 16 + lh];
                float2 u0 = __half22float2(*(__half2*)&q.x);
                float2 u1 = __half22float2(*(__half2*)&q.y);
                float2 u2 = __half22float2(*(__half2*)&q.z);
                float2 u3 = __half22float2(*(__half2*)&q.w);
                acc[0] += u0.x; acc[1] += u0.y; acc[2] += u1.x; acc[3] += u1.y;
                acc[4] += u2.x; acc[5] += u2.y; acc[6] += u3.x; acc[7] += u3.y;
            }
        }
    }

#pragma unroll
    for (int j = 0; j < 8; j++)
        acc[j] += __shfl_xor_sync(0xffffffffu, acc[j], 16);

    float di = g_dinv[node];
    int cb4 = 8 * lh + 4 * hl;
    int o = 4 * hl;

    float4 SC = *(const float4*)&g_sc[layer][cb4];
    float4 TC = *(const float4*)&g_tc[layer][cb4];

    float4 r;
    r.x = fmaxf(fmaf(acc[o + 0] * di, SC.x, TC.x), 0.0f);
    r.y = fmaxf(fmaf(acc[o + 1] * di, SC.y, TC.y), 0.0f);
    r.z = fmaxf(fmaf(acc[o + 2] * di, SC.z, TC.z), 0.0f);
    r.w = fmaxf(fmaf(acc[o + 3] * di, SC.w, TC.w), 0.0f);

    if (prev_sel != 0) {
        float4 p = __ldcs((const float4*)(bufsel(prev_sel) + (size_t)node * DF + cb4));
        r.x += p.x; r.y += p.y; r.z += p.z; r.w += p.w;
    }
    __stcs((float4*)(bufsel(out_sel) + (size_t)node * DF + cb4), r);
}

// ---------------- pooling ----------------
__global__ void k_pool(int x_sel) {
    const float* __restrict__ x = bufsel(x_sel);
    int g = blockIdx.x;
    int t = threadIdx.x;
    int start = (int)(((long long)g * N_NODES + N_GRAPHS - 1) / N_GRAPHS);
    int end   = (int)(((long long)(g + 1) * N_NODES + N_GRAPHS - 1) / N_GRAPHS);
    float sum = 0.0f, mx = -3.4e38f;
    for (int n = start; n < end; n++) {
        float val = __ldcs(&x[(size_t)n * DF + t]);
        sum += val;
        mx = fmaxf(mx, val);
    }
    g_feat[g * 2 * DF + t]      = sum / (float)(end - start);
    g_feat[g * 2 * DF + DF + t] = mx;
}

// ---------------- MLP head ----------------
__global__ void k_mlp(const float* __restrict__ L1w, const float* __restrict__ L1b,
                      const float* __restrict__ L2w, const float* __restrict__ L2b,
                      const float* __restrict__ L3w, const float* __restrict__ L3b,
                      float* __restrict__ out) {
    int g = blockIdx.x;
    int t = threadIdx.x;
    __shared__ float feat[2 * DF];
    __shared__ float h1[DF];
    __shared__ float h2[DF / 2];

    feat[t]      = g_feat[g * 2 * DF + t];
    feat[t + DF] = g_feat[g * 2 * DF + DF + t];
    __syncthreads();

    float a = L1b[t];
#pragma unroll 8
    for (int k = 0; k < 2 * DF; k++)
        a = fmaf(feat[k], L1w[k * DF + t], a);
    h1[t] = fmaxf(a, 0.0f);
    __syncthreads();

    if (t < DF / 2) {
        float a2 = L2b[t];
#pragma unroll 8
        for (int k = 0; k < DF; k++)
            a2 = fmaf(h1[k], L2w[k * (DF / 2) + t], a2);
        h2[t] = fmaxf(a2, 0.0f);
    }
    __syncthreads();

    if (t == 0) {
        float o = L3b[0];
#pragma unroll
        for (int k = 0; k < DF / 2; k++)
            o = fmaf(h2[k], L3w[k], o);
        out[g] = o;
    }
}

// ---------------- launch ----------------
extern "C" void kernel_launch(void* const* d_in, const int* in_sizes, int n_in,
                              void* d_out, int out_size) {
    const float* x  = (const float*)d_in[0];
    const int*   ei = (const int*)d_in[1];   // int32 (JAX x64 disabled)
    const float* W[3]  = {(const float*)d_in[3],  (const float*)d_in[9],  (const float*)d_in[15]};
    const float* cb[3] = {(const float*)d_in[4],  (const float*)d_in[10], (const float*)d_in[16]};
    const float* gg[3] = {(const float*)d_in[5],  (const float*)d_in[11], (const float*)d_in[17]};
    const float* bt[3] = {(const float*)d_in[6],  (const float*)d_in[12], (const float*)d_in[18]};
    const float* m[3]  = {(const float*)d_in[7],  (const float*)d_in[13], (const float*)d_in[19]};
    const float* v[3]  = {(const float*)d_in[8],  (const float*)d_in[14], (const float*)d_in[20]};
    const float* L1w = (const float*)d_in[21];
    const float* L1b = (const float*)d_in[22];
    const float* L2w = (const float*)d_in[23];
    const float* L2b = (const float*)d_in[24];
    const float* L3w = (const float*)d_in[25];
    const float* L3b = (const float*)d_in[26];
    float* out = (float*)d_out;

    // BN constants
    BNP bnp;
    for (int i = 0; i < 3; i++) {
        bnp.g[i] = gg[i]; bnp.v[i] = v[i]; bnp.c[i] = cb[i];
        bnp.m[i] = m[i];  bnp.b[i] = bt[i];
    }
    k_prep<<<1, 384>>>(bnp);

    // CSR build + dinv
    k_zero_cnt<<<(N_NODES + 255) / 256, 256>>>();
    k_count<<<(N_EDGES + 255) / 256, 256>>>(ei);
    k_scanA<<<SCAN_NBLK, SCAN_BLK>>>();
    k_scanB<<<1, 128>>>();
    k_scanC<<<SCAN_NBLK, SCAN_BLK>>>();
    k_fill<<<(N_EDGES + 255) / 256, 256>>>(ei);

    const int gather_grid = (N_NODES * 32 + 255) / 256;      // 12500

    // layer 0
    k_gemm_tc<<<GEMM_BLOCKS, 128>>>(x, W[0], 0);
    k_gather<<<gather_grid, 256>>>(0, 0, 1);

    // layer 1
    k_gemm_tc<<<GEMM_BLOCKS, 128>>>(nullptr, W[1], 1);
    k_gather<<<gather_grid, 256>>>(1, 1, 2);

    // layer 2
    k_gemm_tc<<<GEMM_BLOCKS, 128>>>(nullptr, W[2], 2);
    k_gather<<<gather_grid, 256>>>(2, 2, 1);

    // pooling + MLP head
    k_pool<<<N_GRAPHS, DF>>>(1);
    k_mlp<<<N_GRAPHS, DF>>>(L1w, L1b, L2w, L2b, L3w, L3b, out);
}

// round 11
// speedup vs baseline: 1.7393x; 1.0141x over previous
#include <cuda_runtime.h>
#include <cuda_fp16.h>
#include <cstdint>

#define N_NODES 100000
#define N_EDGES 1600000
#define N_GRAPHS 512
#define DF 128
#define EPS 1e-5f
#define SCAN_BLK 1024
#define SCAN_NBLK ((N_NODES + SCAN_BLK - 1) / SCAN_BLK)   // 98
#define XS_STRIDE 132
#define N_TILES (N_NODES / 32)          // 3125 exact
#define GEMM_BLOCKS 296

// ---------------- scratch (no allocations allowed) ----------------
__device__ __half2 g_h16[N_NODES * (DF / 2)];  // (x @ W) * dinv[row], fp16
__device__ __half2 g_xA [N_NODES * (DF / 2)];  // ping (fp16 node features)
__device__ __half2 g_xB [N_NODES * (DF / 2)];  // pong
__device__ float g_dinv[N_NODES];
__device__ int   g_cnt [N_NODES];
__device__ int   g_off [N_NODES + 1];
__device__ int   g_cur [N_NODES];
__device__ int   g_csr [N_EDGES];       // src ids bucketed by dst
__device__ float g_feat[N_GRAPHS * 2 * DF];
__device__ float g_sc[3][DF];           // BN scale  per layer/col
__device__ float g_tc[3][DF];           // BN offset per layer/col
__device__ int   g_bsum[SCAN_NBLK];
__device__ int   g_bbase[SCAN_NBLK];

__device__ __forceinline__ __half2* bufsel(int s) {
    return (s == 1) ? g_xA : g_xB;
}

// ---------------- BN constant precompute ----------------
struct BNP {
    const float* g[3]; const float* v[3]; const float* c[3];
    const float* m[3]; const float* b[3];
};

__global__ void k_prep(BNP p) {
    int t = threadIdx.x;          // 0..383
    int l = t >> 7, c = t & 127;
    float sc = p.g[l][c] * rsqrtf(p.v[l][c] + EPS);
    g_sc[l][c] = sc;
    g_tc[l][c] = (p.c[l][c] - p.m[l][c]) * sc + p.b[l][c];
}

// ---------------- CSR build ----------------
__global__ void k_zero_cnt() {
    int i = blockIdx.x * blockDim.x + threadIdx.x;
    if (i < N_NODES) g_cnt[i] = 0;
}

__global__ void k_count(const int* __restrict__ ei) {
    int e = blockIdx.x * blockDim.x + threadIdx.x;
    if (e < N_EDGES) atomicAdd(&g_cnt[ei[N_EDGES + e]], 1);
}

__global__ void k_scanA() {
    __shared__ int sh[SCAN_BLK];
    int t = threadIdx.x;
    int b = blockIdx.x;
    int i = b * SCAN_BLK + t;
    int c = (i < N_NODES) ? g_cnt[i] : 0;
    sh[t] = c;
    __syncthreads();
#pragma unroll
    for (int d = 1; d < SCAN_BLK; d <<= 1) {
        int add = (t >= d) ? sh[t - d] : 0;
        __syncthreads();
        sh[t] += add;
        __syncthreads();
    }
    if (i < N_NODES) g_off[i] = sh[t] - c;
    if (t == SCAN_BLK - 1) g_bsum[b] = sh[t];
}

__global__ void k_scanB() {
    __shared__ int sh[128];
    int t = threadIdx.x;
    int v = (t < SCAN_NBLK) ? g_bsum[t] : 0;
    sh[t] = v;
    __syncthreads();
#pragma unroll
    for (int d = 1; d < 128; d <<= 1) {
        int add = (t >= d) ? sh[t - d] : 0;
        __syncthreads();
        sh[t] += add;
        __syncthreads();
    }
    if (t < SCAN_NBLK) g_bbase[t] = sh[t] - v;
    if (t == 127) g_off[N_NODES] = sh[127];
}

__global__ void k_scanC() {
    int t = threadIdx.x;
    int b = blockIdx.x;
    int i = b * SCAN_BLK + t;
    if (i < N_NODES) {
        int off = g_off[i] + g_bbase[b];
        g_off[i] = off;
        g_cur[i] = off;
        g_dinv[i] = rsqrtf((float)g_cnt[i] + 1.0f);
    }
}

__global__ void k_fill(const int* __restrict__ ei) {
    int e = blockIdx.x * blockDim.x + threadIdx.x;
    if (e < N_EDGES) {
        int src = ei[e];
        int dst = ei[N_EDGES + e];
        int pos = atomicAdd(&g_cur[dst], 1);
        g_csr[pos] = src;
    }
}

// ------- GEMM, tf32 mma.m16n8k8, W-in-registers, grid-stride row tiles ----
__device__ __forceinline__ unsigned f2tf32(float f) {
    unsigned u;
    asm("cvt.rna.tf32.f32 %0, %1;" : "=r"(u) : "f"(f));
    return u;
}

__global__ void __launch_bounds__(128, 2) k_gemm_tc(const float* __restrict__ xext,
                                                    const float* __restrict__ W,
                                                    int in_sel) {
    __shared__ unsigned xs[32 * XS_STRIDE];   // 16.9 KB, tf32 x tile

    int tid = threadIdx.x;
    int wy = tid >> 5;        // warp owns cols wy*32 .. wy*32+31
    int lane = tid & 31;
    int g = lane >> 2;        // 0..7
    int t4 = lane & 3;        // 0..3

    // ---- load this lane's B fragments ONCE (128 tf32 regs) ----
    unsigned b[16][4][2];
#pragma unroll
    for (int ks = 0; ks < 16; ks++) {
        int k0 = ks * 8 + t4;
#pragma unroll
        for (int nt = 0; nt < 4; nt++) {
            int n = wy * 32 + nt * 8 + g;
            b[ks][nt][0] = f2tf32(W[k0 * DF + n]);
            b[ks][nt][1] = f2tf32(W[(k0 + 4) * DF + n]);
        }
    }

    const __half2* __restrict__ xh = (in_sel == 0) ? nullptr : bufsel(in_sel);

    for (int tile = blockIdx.x; tile < N_TILES; tile += gridDim.x) {
        int row0 = tile * 32;

        // stage x tile -> tf32 smem (conflict-free padded)
        if (in_sel == 0) {
#pragma unroll
            for (int i = 0; i < 8; i++) {
                int idx = tid + i * 128;     // 0..1023
                int r = idx >> 5;
                int c4 = (idx & 31) * 4;
                float4 v = __ldcs((const float4*)(xext + (size_t)(row0 + r) * DF + c4));
                uint4 tv;
                tv.x = f2tf32(v.x); tv.y = f2tf32(v.y);
                tv.z = f2tf32(v.z); tv.w = f2tf32(v.w);
                *(uint4*)&xs[r * XS_STRIDE + c4] = tv;
            }
        } else {
#pragma unroll
            for (int i = 0; i < 8; i++) {
                int idx = tid + i * 128;
                int r = idx >> 5;
                int u2 = idx & 31;           // 8B unit: cols 4*u2..4*u2+3
                uint2 raw = *(const uint2*)(xh + (size_t)(row0 + r) * 64 + u2 * 2);
                float2 f0 = __half22float2(*(__half2*)&raw.x);
                float2 f1 = __half22float2(*(__half2*)&raw.y);
                uint4 tv;
                tv.x = f2tf32(f0.x); tv.y = f2tf32(f0.y);
                tv.z = f2tf32(f1.x); tv.w = f2tf32(f1.y);
                *(uint4*)&xs[r * XS_STRIDE + u2 * 4] = tv;
            }
        }
        __syncthreads();

        float c[2][4][4];
#pragma unroll
        for (int m = 0; m < 2; m++)
#pragma unroll
            for (int nt = 0; nt < 4; nt++) {
                c[m][nt][0] = 0.f; c[m][nt][1] = 0.f;
                c[m][nt][2] = 0.f; c[m][nt][3] = 0.f;
            }

#pragma unroll
        for (int ks = 0; ks < 16; ks++) {
            int kc = ks * 8 + t4;
#pragma unroll
            for (int m = 0; m < 2; m++) {
                unsigned a0 = xs[(m * 16 + g) * XS_STRIDE + kc];
                unsigned a1 = xs[(m * 16 + g + 8) * XS_STRIDE + kc];
                unsigned a2 = xs[(m * 16 + g) * XS_STRIDE + kc + 4];
                unsigned a3 = xs[(m * 16 + g + 8) * XS_STRIDE + kc + 4];
#pragma unroll
                for (int nt = 0; nt < 4; nt++) {
                    asm volatile(
                        "mma.sync.aligned.m16n8k8.row.col.f32.tf32.tf32.f32 "
                        "{%0,%1,%2,%3}, {%4,%5,%6,%7}, {%8,%9}, {%0,%1,%2,%3};"
                        : "+f"(c[m][nt][0]), "+f"(c[m][nt][1]),
                          "+f"(c[m][nt][2]), "+f"(c[m][nt][3])
                        : "r"(a0), "r"(a1), "r"(a2), "r"(a3),
                          "r"(b[ks][nt][0]), "r"(b[ks][nt][1]));
                }
            }
        }

        // epilogue: scale by dinv, pack half2, store
#pragma unroll
        for (int m = 0; m < 2; m++) {
            int row_a = row0 + m * 16 + g;
            int row_b = row_a + 8;
            float dva = g_dinv[row_a];
            float dvb = g_dinv[row_b];
#pragma unroll
            for (int nt = 0; nt < 4; nt++) {
                int col2 = wy * 16 + nt * 4 + t4;   // half2 unit index
                g_h16[(size_t)row_a * 64 + col2] =
                    __floats2half2_rn(c[m][nt][0] * dva, c[m][nt][1] * dva);
                g_h16[(size_t)row_b * 64 + col2] =
                    __floats2half2_rn(c[m][nt][2] * dvb, c[m][nt][3] * dvb);
            }
        }
        __syncthreads();
    }
}

// ------- gather + BN + ReLU + residual: ONE warp per node, pair scheme -----
__global__ void k_gather(int layer, int prev_sel, int out_sel) {
    int node = (blockIdx.x * blockDim.x + threadIdx.x) >> 5;
    int lane = threadIdx.x & 31;
    if (node >= N_NODES) return;
    int hl = lane >> 4;
    int lh = lane & 15;

    int beg = g_off[node];
    int end = g_off[node + 1];

    const uint4* __restrict__ H = (const uint4*)g_h16;

    float acc[8];
#pragma unroll
    for (int j = 0; j < 8; j++) acc[j] = 0.0f;

    if (hl == 0) {
        uint4 q = H[(size_t)node * 16 + lh];
        float2 u0 = __half22float2(*(__half2*)&q.x);
        float2 u1 = __half22float2(*(__half2*)&q.y);
        float2 u2 = __half22float2(*(__half2*)&q.z);
        float2 u3 = __half22float2(*(__half2*)&q.w);
        acc[0] = u0.x; acc[1] = u0.y; acc[2] = u1.x; acc[3] = u1.y;
        acc[4] = u2.x; acc[5] = u2.y; acc[6] = u3.x; acc[7] = u3.y;
    }

    for (int j0 = beg; j0 < end; j0 += 32) {
        int cntc = min(end - j0, 32);
        int idx = (lane < cntc) ? g_csr[j0 + lane] : 0;
        int steps = (cntc + 1) >> 1;
        for (int k = 0; k < steps; k++) {
            int e = 2 * k + hl;
            int srcl = (e < cntc) ? e : 0;
            int s = __shfl_sync(0xffffffffu, idx, srcl);
            if (e < cntc) {
                uint4 q = H[(size_t)s * 16 + lh];
                float2 u0 = __half22float2(*(__half2*)&q.x);
                float2 u1 = __half22float2(*(__half2*)&q.y);
                float2 u2 = __half22float2(*(__half2*)&q.z);
                float2 u3 = __half22float2(*(__half2*)&q.w);
                acc[0] += u0.x; acc[1] += u0.y; acc[2] += u1.x; acc[3] += u1.y;
                acc[4] += u2.x; acc[5] += u2.y; acc[6] += u3.x; acc[7] += u3.y;
            }
        }
    }

#pragma unroll
    for (int j = 0; j < 8; j++)
        acc[j] += __shfl_xor_sync(0xffffffffu, acc[j], 16);

    float di = g_dinv[node];
    int cb4 = 8 * lh + 4 * hl;           // 4 consecutive cols
    int o = 4 * hl;

    float4 SC = *(const float4*)&g_sc[layer][cb4];
    float4 TC = *(const float4*)&g_tc[layer][cb4];

    float r0 = fmaxf(fmaf(acc[o + 0] * di, SC.x, TC.x), 0.0f);
    float r1 = fmaxf(fmaf(acc[o + 1] * di, SC.y, TC.y), 0.0f);
    float r2 = fmaxf(fmaf(acc[o + 2] * di, SC.z, TC.z), 0.0f);
    float r3 = fmaxf(fmaf(acc[o + 3] * di, SC.w, TC.w), 0.0f);

    if (prev_sel != 0) {
        uint2 p = *(const uint2*)(bufsel(prev_sel) + (size_t)node * 64 + (cb4 >> 1));
        float2 p0 = __half22float2(*(__half2*)&p.x);
        float2 p1 = __half22float2(*(__half2*)&p.y);
        r0 += p0.x; r1 += p0.y; r2 += p1.x; r3 += p1.y;
    }

    __half2 h0 = __floats2half2_rn(r0, r1);
    __half2 h1 = __floats2half2_rn(r2, r3);
    uint2 ov;
    ov.x = *(unsigned*)&h0;
    ov.y = *(unsigned*)&h1;
    *(uint2*)(bufsel(out_sel) + (size_t)node * 64 + (cb4 >> 1)) = ov;
}

// ---------------- pooling: per-graph mean & max (contiguous ranges) ------
// 64 threads/block; thread t handles cols 2t, 2t+1 (one half2 unit)
__global__ void k_pool(int x_sel) {
    const __half2* __restrict__ x = bufsel(x_sel);
    int g = blockIdx.x;
    int t = threadIdx.x;   // 0..63
    int start = (int)(((long long)g * N_NODES + N_GRAPHS - 1) / N_GRAPHS);
    int end   = (int)(((long long)(g + 1) * N_NODES + N_GRAPHS - 1) / N_GRAPHS);
    float s0 = 0.f, s1 = 0.f, m0 = -3.4e38f, m1 = -3.4e38f;
    for (int n = start; n < end; n++) {
        float2 f = __half22float2(x[(size_t)n * 64 + t]);
        s0 += f.x; s1 += f.y;
        m0 = fmaxf(m0, f.x); m1 = fmaxf(m1, f.y);
    }
    float inv = 1.0f / (float)(end - start);
    g_feat[g * 2 * DF + 2 * t]         = s0 * inv;
    g_feat[g * 2 * DF + 2 * t + 1]     = s1 * inv;
    g_feat[g * 2 * DF + DF + 2 * t]    = m0;
    g_feat[g * 2 * DF + DF + 2 * t + 1] = m1;
}

// ---------------- MLP head ----------------
__global__ void k_mlp(const float* __restrict__ L1w, const float* __restrict__ L1b,
                      const float* __restrict__ L2w, const float* __restrict__ L2b,
                      const float* __restrict__ L3w, const float* __restrict__ L3b,
                      float* __restrict__ out) {
    int g = blockIdx.x;
    int t = threadIdx.x;
    __shared__ float feat[2 * DF];
    __shared__ float h1[DF];
    __shared__ float h2[DF / 2];

    feat[t]      = g_feat[g * 2 * DF + t];
    feat[t + DF] = g_feat[g * 2 * DF + DF + t];
    __syncthreads();

    float a = L1b[t];
#pragma unroll 8
    for (int k = 0; k < 2 * DF; k++)
        a = fmaf(feat[k], L1w[k * DF + t], a);
    h1[t] = fmaxf(a, 0.0f);
    __syncthreads();

    if (t < DF / 2) {
        float a2 = L2b[t];
#pragma unroll 8
        for (int k = 0; k < DF; k++)
            a2 = fmaf(h1[k], L2w[k * (DF / 2) + t], a2);
        h2[t] = fmaxf(a2, 0.0f);
    }
    __syncthreads();

    if (t == 0) {
        float o = L3b[0];
#pragma unroll
        for (int k = 0; k < DF / 2; k++)
            o = fmaf(h2[k], L3w[k], o);
        out[g] = o;
    }
}

// ---------------- launch ----------------
extern "C" void kernel_launch(void* const* d_in, const int* in_sizes, int n_in,
                              void* d_out, int out_size) {
    const float* x  = (const float*)d_in[0];
    const int*   ei = (const int*)d_in[1];   // int32 (JAX x64 disabled)
    const float* W[3]  = {(const float*)d_in[3],  (const float*)d_in[9],  (const float*)d_in[15]};
    const float* cb[3] = {(const float*)d_in[4],  (const float*)d_in[10], (const float*)d_in[16]};
    const float* gg[3] = {(const float*)d_in[5],  (const float*)d_in[11], (const float*)d_in[17]};
    const float* bt[3] = {(const float*)d_in[6],  (const float*)d_in[12], (const float*)d_in[18]};
    const float* m[3]  = {(const float*)d_in[7],  (const float*)d_in[13], (const float*)d_in[19]};
    const float* v[3]  = {(const float*)d_in[8],  (const float*)d_in[14], (const float*)d_in[20]};
    const float* L1w = (const float*)d_in[21];
    const float* L1b = (const float*)d_in[22];
    const float* L2w = (const float*)d_in[23];
    const float* L2b = (const float*)d_in[24];
    const float* L3w = (const float*)d_in[25];
    const float* L3b = (const float*)d_in[26];
    float* out = (float*)d_out;

    // BN constants
    BNP bnp;
    for (int i = 0; i < 3; i++) {
        bnp.g[i] = gg[i]; bnp.v[i] = v[i]; bnp.c[i] = cb[i];
        bnp.m[i] = m[i];  bnp.b[i] = bt[i];
    }
    k_prep<<<1, 384>>>(bnp);

    // CSR build + dinv
    k_zero_cnt<<<(N_NODES + 255) / 256, 256>>>();
    k_count<<<(N_EDGES + 255) / 256, 256>>>(ei);
    k_scanA<<<SCAN_NBLK, SCAN_BLK>>>();
    k_scanB<<<1, 128>>>();
    k_scanC<<<SCAN_NBLK, SCAN_BLK>>>();
    k_fill<<<(N_EDGES + 255) / 256, 256>>>(ei);

    const int gather_grid = (N_NODES * 32 + 255) / 256;      // 12500

    // layer 0
    k_gemm_tc<<<GEMM_BLOCKS, 128>>>(x, W[0], 0);
    k_gather<<<gather_grid, 256>>>(0, 0, 1);

    // layer 1
    k_gemm_tc<<<GEMM_BLOCKS, 128>>>(nullptr, W[1], 1);
    k_gather<<<gather_grid, 256>>>(1, 1, 2);

    // layer 2
    k_gemm_tc<<<GEMM_BLOCKS, 128>>>(nullptr, W[2], 2);
    k_gather<<<gather_grid, 256>>>(2, 2, 1);

    // pooling + MLP head
    k_pool<<<N_GRAPHS, 64>>>(1);
    k_mlp<<<N_GRAPHS, DF>>>(L1w, L1b, L2w, L2b, L3w, L3b, out);
}

// round 12
// speedup vs baseline: 1.8089x; 1.0400x over previous
#include <cuda_runtime.h>
#include <cuda_fp16.h>
#include <cstdint>

#define N_NODES 100000
#define N_EDGES 1600000
#define N_GRAPHS 512
#define DF 128
#define EPS 1e-5f
#define SCAN_BLK 1024
#define SCAN_NBLK ((N_NODES + SCAN_BLK - 1) / SCAN_BLK)   // 98
#define XS_STRIDE 132
#define N_TILES (N_NODES / 32)          // 3125 exact
#define GEMM_BLOCKS 296

// ---------------- scratch (no allocations allowed) ----------------
__device__ __half2 g_h16[N_NODES * (DF / 2)];  // (x @ W) * dinv[row], fp16
__device__ __half2 g_xA [N_NODES * (DF / 2)];  // ping (fp16 node features)
__device__ __half2 g_xB [N_NODES * (DF / 2)];  // pong
__device__ float g_dinv[N_NODES];
__device__ int   g_cnt [N_NODES];       // ALWAYS zero between calls (self-restoring)
__device__ int   g_off [N_NODES + 1];
__device__ int   g_cur [N_NODES];
__device__ int   g_csr [N_EDGES];       // src ids bucketed by dst
__device__ float g_feat[N_GRAPHS * 2 * DF];
__device__ float g_sc[3][DF];           // BN scale  per layer/col
__device__ float g_tc[3][DF];           // BN offset per layer/col
__device__ int   g_bsum[SCAN_NBLK];
__device__ int   g_bbase[SCAN_NBLK];

__device__ __forceinline__ __half2* bufsel(int s) {
    return (s == 1) ? g_xA : g_xB;
}

struct BNP {
    const float* g[3]; const float* v[3]; const float* c[3];
    const float* m[3]; const float* b[3];
};

// ---------------- CSR build ----------------
// 4 edges per thread via int4
__global__ void k_count(const int* __restrict__ ei) {
    int i = blockIdx.x * blockDim.x + threadIdx.x;
    if (i < N_EDGES / 4) {
        int4 d = ((const int4*)(ei + N_EDGES))[i];
        atomicAdd(&g_cnt[d.x], 1);
        atomicAdd(&g_cnt[d.y], 1);
        atomicAdd(&g_cnt[d.z], 1);
        atomicAdd(&g_cnt[d.w], 1);
    }
}

// per-block scan; also emits dinv and re-zeroes g_cnt for the next call
__global__ void k_scanA() {
    __shared__ int sh[SCAN_BLK];
    int t = threadIdx.x;
    int b = blockIdx.x;
    int i = b * SCAN_BLK + t;
    int c = 0;
    if (i < N_NODES) {
        c = g_cnt[i];
        g_cnt[i] = 0;                             // restore invariant
        g_dinv[i] = rsqrtf((float)c + 1.0f);      // +1 self loop
    }
    sh[t] = c;
    __syncthreads();
#pragma unroll
    for (int d = 1; d < SCAN_BLK; d <<= 1) {
        int add = (t >= d) ? sh[t - d] : 0;
        __syncthreads();
        sh[t] += add;
        __syncthreads();
    }
    if (i < N_NODES) g_off[i] = sh[t] - c;
    if (t == SCAN_BLK - 1) g_bsum[b] = sh[t];
}

// merged: BN constant precompute (threads 0..383) + block-sum scan (384..511)
__global__ void k_prep_scanB(BNP p) {
    __shared__ int sh[128];
    int t = threadIdx.x;    // 0..511
    if (t < 384) {
        int l = t >> 7, c = t & 127;
        float sc = p.g[l][c] * rsqrtf(p.v[l][c] + EPS);
        g_sc[l][c] = sc;
        g_tc[l][c] = (p.c[l][c] - p.m[l][c]) * sc + p.b[l][c];
    }
    int s = t - 384;
    int v = 0;
    if (s >= 0) {
        v = (s < SCAN_NBLK) ? g_bsum[s] : 0;
        sh[s] = v;
    }
    __syncthreads();
#pragma unroll
    for (int d = 1; d < 128; d <<= 1) {
        int add = (s >= d) ? sh[s - d] : 0;
        __syncthreads();
        if (s >= 0) sh[s] += add;
        __syncthreads();
    }
    if (s >= 0 && s < SCAN_NBLK) g_bbase[s] = sh[s] - v;
    if (s == 127) g_off[N_NODES] = sh[127];
}

__global__ void k_scanC() {
    int i = blockIdx.x * blockDim.x + threadIdx.x;
    if (i < N_NODES) {
        int off = g_off[i] + g_bbase[i / SCAN_BLK];
        g_off[i] = off;
        g_cur[i] = off;
    }
}

__global__ void k_fill(const int* __restrict__ ei) {
    int i = blockIdx.x * blockDim.x + threadIdx.x;
    if (i < N_EDGES / 4) {
        int4 s = ((const int4*)ei)[i];
        int4 d = ((const int4*)(ei + N_EDGES))[i];
        g_csr[atomicAdd(&g_cur[d.x], 1)] = s.x;
        g_csr[atomicAdd(&g_cur[d.y], 1)] = s.y;
        g_csr[atomicAdd(&g_cur[d.z], 1)] = s.z;
        g_csr[atomicAdd(&g_cur[d.w], 1)] = s.w;
    }
}

// ------- GEMM, tf32 mma.m16n8k8, W-in-registers, grid-stride row tiles ----
__device__ __forceinline__ unsigned f2tf32(float f) {
    unsigned u;
    asm("cvt.rna.tf32.f32 %0, %1;" : "=r"(u) : "f"(f));
    return u;
}

__global__ void __launch_bounds__(128, 2) k_gemm_tc(const float* __restrict__ xext,
                                                    const float* __restrict__ W,
                                                    int in_sel) {
    __shared__ unsigned xs[32 * XS_STRIDE];   // 16.9 KB, tf32 x tile

    int tid = threadIdx.x;
    int wy = tid >> 5;        // warp owns cols wy*32 .. wy*32+31
    int lane = tid & 31;
    int g = lane >> 2;        // 0..7
    int t4 = lane & 3;        // 0..3

    // ---- load this lane's B fragments ONCE (128 tf32 regs) ----
    unsigned b[16][4][2];
#pragma unroll
    for (int ks = 0; ks < 16; ks++) {
        int k0 = ks * 8 + t4;
#pragma unroll
        for (int nt = 0; nt < 4; nt++) {
            int n = wy * 32 + nt * 8 + g;
            b[ks][nt][0] = f2tf32(W[k0 * DF + n]);
            b[ks][nt][1] = f2tf32(W[(k0 + 4) * DF + n]);
        }
    }

    const __half2* __restrict__ xh = (in_sel == 0) ? nullptr : bufsel(in_sel);

    for (int tile = blockIdx.x; tile < N_TILES; tile += gridDim.x) {
        int row0 = tile * 32;

        if (in_sel == 0) {
#pragma unroll
            for (int i = 0; i < 8; i++) {
                int idx = tid + i * 128;     // 0..1023
                int r = idx >> 5;
                int c4 = (idx & 31) * 4;
                float4 v = __ldcs((const float4*)(xext + (size_t)(row0 + r) * DF + c4));
                uint4 tv;
                tv.x = f2tf32(v.x); tv.y = f2tf32(v.y);
                tv.z = f2tf32(v.z); tv.w = f2tf32(v.w);
                *(uint4*)&xs[r * XS_STRIDE + c4] = tv;
            }
        } else {
#pragma unroll
            for (int i = 0; i < 8; i++) {
                int idx = tid + i * 128;
                int r = idx >> 5;
                int u2 = idx & 31;           // 8B unit: cols 4*u2..4*u2+3
                uint2 raw = *(const uint2*)(xh + (size_t)(row0 + r) * 64 + u2 * 2);
                float2 f0 = __half22float2(*(__half2*)&raw.x);
                float2 f1 = __half22float2(*(__half2*)&raw.y);
                uint4 tv;
                tv.x = f2tf32(f0.x); tv.y = f2tf32(f0.y);
                tv.z = f2tf32(f1.x); tv.w = f2tf32(f1.y);
                *(uint4*)&xs[r * XS_STRIDE + u2 * 4] = tv;
            }
        }
        __syncthreads();

        float c[2][4][4];
#pragma unroll
        for (int m = 0; m < 2; m++)
#pragma unroll
            for (int nt = 0; nt < 4; nt++) {
                c[m][nt][0] = 0.f; c[m][nt][1] = 0.f;
                c[m][nt][2] = 0.f; c[m][nt][3] = 0.f;
            }

#pragma unroll
        for (int ks = 0; ks < 16; ks++) {
            int kc = ks * 8 + t4;
#pragma unroll
            for (int m = 0; m < 2; m++) {
                unsigned a0 = xs[(m * 16 + g) * XS_STRIDE + kc];
                unsigned a1 = xs[(m * 16 + g + 8) * XS_STRIDE + kc];
                unsigned a2 = xs[(m * 16 + g) * XS_STRIDE + kc + 4];
                unsigned a3 = xs[(m * 16 + g + 8) * XS_STRIDE + kc + 4];
#pragma unroll
                for (int nt = 0; nt < 4; nt++) {
                    asm volatile(
                        "mma.sync.aligned.m16n8k8.row.col.f32.tf32.tf32.f32 "
                        "{%0,%1,%2,%3}, {%4,%5,%6,%7}, {%8,%9}, {%0,%1,%2,%3};"
                        : "+f"(c[m][nt][0]), "+f"(c[m][nt][1]),
                          "+f"(c[m][nt][2]), "+f"(c[m][nt][3])
                        : "r"(a0), "r"(a1), "r"(a2), "r"(a3),
                          "r"(b[ks][nt][0]), "r"(b[ks][nt][1]));
                }
            }
        }

#pragma unroll
        for (int m = 0; m < 2; m++) {
            int row_a = row0 + m * 16 + g;
            int row_b = row_a + 8;
            float dva = g_dinv[row_a];
            float dvb = g_dinv[row_b];
#pragma unroll
            for (int nt = 0; nt < 4; nt++) {
                int col2 = wy * 16 + nt * 4 + t4;   // half2 unit index
                g_h16[(size_t)row_a * 64 + col2] =
                    __floats2half2_rn(c[m][nt][0] * dva, c[m][nt][1] * dva);
                g_h16[(size_t)row_b * 64 + col2] =
                    __floats2half2_rn(c[m][nt][2] * dvb, c[m][nt][3] * dvb);
            }
        }
        __syncthreads();
    }
}

// ------- gather + BN + ReLU + residual: ONE warp per node, pair scheme -----
__global__ void k_gather(int layer, int prev_sel, int out_sel) {
    int node = (blockIdx.x * blockDim.x + threadIdx.x) >> 5;
    int lane = threadIdx.x & 31;
    if (node >= N_NODES) return;
    int hl = lane >> 4;
    int lh = lane & 15;

    int beg = g_off[node];
    int end = g_off[node + 1];

    const uint4* __restrict__ H = (const uint4*)g_h16;

    float acc[8];
#pragma unroll
    for (int j = 0; j < 8; j++) acc[j] = 0.0f;

    if (hl == 0) {
        uint4 q = H[(size_t)node * 16 + lh];
        float2 u0 = __half22float2(*(__half2*)&q.x);
        float2 u1 = __half22float2(*(__half2*)&q.y);
        float2 u2 = __half22float2(*(__half2*)&q.z);
        float2 u3 = __half22float2(*(__half2*)&q.w);
        acc[0] = u0.x; acc[1] = u0.y; acc[2] = u1.x; acc[3] = u1.y;
        acc[4] = u2.x; acc[5] = u2.y; acc[6] = u3.x; acc[7] = u3.y;
    }

    for (int j0 = beg; j0 < end; j0 += 32) {
        int cntc = min(end - j0, 32);
        int idx = (lane < cntc) ? g_csr[j0 + lane] : 0;
        int steps = (cntc + 1) >> 1;
        for (int k = 0; k < steps; k++) {
            int e = 2 * k + hl;
            int srcl = (e < cntc) ? e : 0;
            int s = __shfl_sync(0xffffffffu, idx, srcl);
            if (e < cntc) {
                uint4 q = H[(size_t)s * 16 + lh];
                float2 u0 = __half22float2(*(__half2*)&q.x);
                float2 u1 = __half22float2(*(__half2*)&q.y);
                float2 u2 = __half22float2(*(__half2*)&q.z);
                float2 u3 = __half22float2(*(__half2*)&q.w);
                acc[0] += u0.x; acc[1] += u0.y; acc[2] += u1.x; acc[3] += u1.y;
                acc[4] += u2.x; acc[5] += u2.y; acc[6] += u3.x; acc[7] += u3.y;
            }
        }
    }

#pragma unroll
    for (int j = 0; j < 8; j++)
        acc[j] += __shfl_xor_sync(0xffffffffu, acc[j], 16);

    float di = g_dinv[node];
    int cb4 = 8 * lh + 4 * hl;           // 4 consecutive cols
    int o = 4 * hl;

    float4 SC = *(const float4*)&g_sc[layer][cb4];
    float4 TC = *(const float4*)&g_tc[layer][cb4];

    float r0 = fmaxf(fmaf(acc[o + 0] * di, SC.x, TC.x), 0.0f);
    float r1 = fmaxf(fmaf(acc[o + 1] * di, SC.y, TC.y), 0.0f);
    float r2 = fmaxf(fmaf(acc[o + 2] * di, SC.z, TC.z), 0.0f);
    float r3 = fmaxf(fmaf(acc[o + 3] * di, SC.w, TC.w), 0.0f);

    if (prev_sel != 0) {
        uint2 p = *(const uint2*)(bufsel(prev_sel) + (size_t)node * 64 + (cb4 >> 1));
        float2 p0 = __half22float2(*(__half2*)&p.x);
        float2 p1 = __half22float2(*(__half2*)&p.y);
        r0 += p0.x; r1 += p0.y; r2 += p1.x; r3 += p1.y;
    }

    __half2 h0 = __floats2half2_rn(r0, r1);
    __half2 h1 = __floats2half2_rn(r2, r3);
    uint2 ov;
    ov.x = *(unsigned*)&h0;
    ov.y = *(unsigned*)&h1;
    *(uint2*)(bufsel(out_sel) + (size_t)node * 64 + (cb4 >> 1)) = ov;
}

// ---------------- fused pooling + MLP head ----------------
__global__ void k_poolmlp(const float* __restrict__ L1w, const float* __restrict__ L1b,
                          const float* __restrict__ L2w, const float* __restrict__ L2b,
                          const float* __restrict__ L3w, const float* __restrict__ L3b,
                          float* __restrict__ out, int x_sel) {
    int g = blockIdx.x;
    int t = threadIdx.x;     // 0..127
    __shared__ float feat[2 * DF];
    __shared__ float h1[DF];
    __shared__ float h2[DF / 2];

    const __half* __restrict__ x = (const __half*)bufsel(x_sel);
    int start = (int)(((long long)g * N_NODES + N_GRAPHS - 1) / N_GRAPHS);
    int end   = (int)(((long long)(g + 1) * N_NODES + N_GRAPHS - 1) / N_GRAPHS);
    float sum = 0.0f, mx = -3.4e38f;
    for (int n = start; n < end; n++) {
        float val = __half2float(x[(size_t)n * DF + t]);
        sum += val;
        mx = fmaxf(mx, val);
    }
    feat[t]      = sum / (float)(end - start);
    feat[t + DF] = mx;
    __syncthreads();

    float a = L1b[t];
#pragma unroll 8
    for (int k = 0; k < 2 * DF; k++)
        a = fmaf(feat[k], L1w[k * DF + t], a);
    h1[t] = fmaxf(a, 0.0f);
    __syncthreads();

    if (t < DF / 2) {
        float a2 = L2b[t];
#pragma unroll 8
        for (int k = 0; k < DF; k++)
            a2 = fmaf(h1[k], L2w[k * (DF / 2) + t], a2);
        h2[t] = fmaxf(a2, 0.0f);
    }
    __syncthreads();

    if (t == 0) {
        float o = L3b[0];
#pragma unroll
        for (int k = 0; k < DF / 2; k++)
            o = fmaf(h2[k], L3w[k], o);
        out[g] = o;
    }
}

// ---------------- launch ----------------
extern "C" void kernel_launch(void* const* d_in, const int* in_sizes, int n_in,
                              void* d_out, int out_size) {
    const float* x  = (const float*)d_in[0];
    const int*   ei = (const int*)d_in[1];   // int32 (JAX x64 disabled)
    const float* W[3]  = {(const float*)d_in[3],  (const float*)d_in[9],  (const float*)d_in[15]};
    const float* cb[3] = {(const float*)d_in[4],  (const float*)d_in[10], (const float*)d_in[16]};
    const float* gg[3] = {(const float*)d_in[5],  (const float*)d_in[11], (const float*)d_in[17]};
    const float* bt[3] = {(const float*)d_in[6],  (const float*)d_in[12], (const float*)d_in[18]};
    const float* m[3]  = {(const float*)d_in[7],  (const float*)d_in[13], (const float*)d_in[19]};
    const float* v[3]  = {(const float*)d_in[8],  (const float*)d_in[14], (const float*)d_in[20]};
    const float* L1w = (const float*)d_in[21];
    const float* L1b = (const float*)d_in[22];
    const float* L2w = (const float*)d_in[23];
    const float* L2b = (const float*)d_in[24];
    const float* L3w = (const float*)d_in[25];
    const float* L3b = (const float*)d_in[26];
    float* out = (float*)d_out;

    BNP bnp;
    for (int i = 0; i < 3; i++) {
        bnp.g[i] = gg[i]; bnp.v[i] = v[i]; bnp.c[i] = cb[i];
        bnp.m[i] = m[i];  bnp.b[i] = bt[i];
    }

    // CSR build + dinv (g_cnt arrives zeroed; scanA restores it)
    const int e4_grid = (N_EDGES / 4 + 255) / 256;           // 1563
    k_count<<<e4_grid, 256>>>(ei);
    k_scanA<<<SCAN_NBLK, SCAN_BLK>>>();
    k_prep_scanB<<<1, 512>>>(bnp);
    k_scanC<<<(N_NODES + 1023) / 1024, 1024>>>();
    k_fill<<<e4_grid, 256>>>(ei);

    const int gather_grid = (N_NODES * 32 + 255) / 256;      // 12500

    // layer 0
    k_gemm_tc<<<GEMM_BLOCKS, 128>>>(x, W[0], 0);
    k_gather<<<gather_grid, 256>>>(0, 0, 1);

    // layer 1
    k_gemm_tc<<<GEMM_BLOCKS, 128>>>(nullptr, W[1], 1);
    k_gather<<<gather_grid, 256>>>(1, 1, 2);

    // layer 2
    k_gemm_tc<<<GEMM_BLOCKS, 128>>>(nullptr, W[2], 2);
    k_gather<<<gather_grid, 256>>>(2, 2, 1);

    // fused pooling + MLP head
    k_poolmlp<<<N_GRAPHS, DF>>>(L1w, L1b, L2w, L2b, L3w, L3b, out, 1);
}